// round 1
// baseline (speedup 1.0000x reference)
#include <cuda_runtime.h>

// SphKernel: out[b,v,p,n,c] = g_n(r) * Y_c(rotate(frame, normalize(patch)))
// B=4, V=4096, P=64, NR=3, C=16. Total points = 1,048,576; out = 48 f32/point.
//
// Strategy: 1 thread per point computes all 48 values, stages them in padded
// shared memory (stride 49 -> conflict-free STS), then the block does a fully
// coalesced float4 write-out.

#define TPB 128           // threads per block == points per block
#define SH_STRIDE 49      // 48 + 1 pad: (49*t + j) % 32 = (17t + j) % 32, all distinct
#define FLOATS_PER_BLOCK (TPB * 48)   // 6144
#define VEC4_PER_BLOCK   (FLOATS_PER_BLOCK / 4)  // 1536

__global__ __launch_bounds__(TPB)
void sph_kernel(const float* __restrict__ patches,
                const float* __restrict__ frames,
                const float* __restrict__ r,
                float* __restrict__ out)
{
    __shared__ float sh[TPB * SH_STRIDE];   // 25088 B

    const int tid = threadIdx.x;
    const int pt  = blockIdx.x * TPB + tid;   // global point index
    const int fi  = pt >> 6;                  // frame index (P = 64)

    // ---- load & normalize direction ----
    const float px = __ldg(patches + 3 * pt + 0);
    const float py = __ldg(patches + 3 * pt + 1);
    const float pz = __ldg(patches + 3 * pt + 2);
    const float sq  = px * px + py * py + pz * pz;
    const float inv = rsqrtf(fmaxf(sq, 1e-12f));
    const float dx = px * inv, dy = py * inv, dz = pz * inv;

    // ---- rotate into local frame: proj_j = sum_i F[i][j] * d_i ----
    const float* F = frames + 9 * fi;         // warp-uniform -> broadcast LDG
    const float f0 = __ldg(F + 0), f1 = __ldg(F + 1), f2 = __ldg(F + 2);
    const float f3 = __ldg(F + 3), f4 = __ldg(F + 4), f5 = __ldg(F + 5);
    const float f6 = __ldg(F + 6), f7 = __ldg(F + 7), f8 = __ldg(F + 8);
    const float x = f0 * dx + f3 * dy + f6 * dz;
    const float y = f1 * dx + f4 * dy + f7 * dz;
    const float z = f2 * dx + f5 * dy + f8 * dz;

    // ---- spherical harmonics, channel order per reference ----
    const float x2 = x * x, y2 = y * y, z2 = z * z;
    const float xy = x * y, yz = y * z, zx = z * x;

    float Y[16];
    Y[0]  = 0.28209479177387814f;                          // Y00
    Y[1]  = 0.4886025119029199f * z;                       // Y10
    Y[2]  = 0.31539156525252005f * (2.f * z2 - x2 - y2);   // Y20
    Y[3]  = 0.3731763325901154f * z * (2.f * z2 - 3.f * x2 - 3.f * y2); // Y30
    Y[4]  = 0.4886025119029199f * x;                       // Y1_10
    Y[5]  = 0.4886025119029199f * y;                       // Y1_11
    Y[6]  = 1.0925484305920792f * zx;                      // Y2_10
    Y[7]  = 1.0925484305920792f * yz;                      // Y2_11
    Y[8]  = 0.4570457994644658f * x * (4.f * z2 - x2 - y2); // Y3_10
    Y[9]  = 0.4570457994644658f * y * (4.f * z2 - x2 - y2); // Y3_11
    Y[10] = 0.5462742152960396f * (x2 - y2);               // Y2_20
    Y[11] = 1.0925484305920792f * xy;                      // Y2_21
    Y[12] = 1.4453057213202771f * z * (x2 - y2);           // Y3_20
    Y[13] = 2.8906114426405543f * xy * z;                  // Y3_21
    Y[14] = 0.5900435899266435f * x * (x2 - 3.f * y2);     // Y3_30
    Y[15] = 0.5900435899266435f * y * (3.f * x2 - y2);     // Y3_31

    // ---- gaussian shells: centers {0, 0.5, 1}, exp(4*ln(0.5)*d^2), normalized ----
    const float rv = __ldg(r + pt);
    const float K = -2.772588722239781f;   // 4 * ln(0.5)
    const float d0 = rv, d1 = rv - 0.5f, d2 = rv - 1.0f;
    float g0 = __expf(K * d0 * d0);
    float g1 = __expf(K * d1 * d1);
    float g2 = __expf(K * d2 * d2);
    const float ginv = 1.0f / (g0 + g1 + g2);
    g0 *= ginv; g1 *= ginv; g2 *= ginv;

    // ---- stage 48 outputs in padded shared (conflict-free per STS) ----
    float* row = sh + tid * SH_STRIDE;
#pragma unroll
    for (int c = 0; c < 16; c++) row[c]      = g0 * Y[c];
#pragma unroll
    for (int c = 0; c < 16; c++) row[16 + c] = g1 * Y[c];
#pragma unroll
    for (int c = 0; c < 16; c++) row[32 + c] = g2 * Y[c];

    __syncthreads();

    // ---- coalesced float4 write-out ----
    float4* out4 = reinterpret_cast<float4*>(out);
    const size_t base = (size_t)blockIdx.x * VEC4_PER_BLOCK;
#pragma unroll
    for (int k = 0; k < 12; k++) {
        const int f = k * (TPB * 4) + tid * 4;  // float index within block tile
        const int p = f / 48;                   // point within block
        const int c = f - p * 48;               // channel*shell offset (multiple of 4)
        const float* s = sh + p * SH_STRIDE + c;
        float4 v = make_float4(s[0], s[1], s[2], s[3]);
        out4[base + (size_t)k * TPB + tid] = v;
    }
}

extern "C" void kernel_launch(void* const* d_in, const int* in_sizes, int n_in,
                              void* d_out, int out_size)
{
    const float* patches = (const float*)d_in[0];  // [4,4096,64,3]
    const float* frames  = (const float*)d_in[1];  // [4,4096,3,3]
    const float* r       = (const float*)d_in[2];  // [4,4096,64]
    float* out = (float*)d_out;                    // [4,4096,64,3,16]

    const int total_points = in_sizes[2];          // B*V*P = 1,048,576
    const int blocks = total_points / TPB;         // 8192

    sph_kernel<<<blocks, TPB>>>(patches, frames, r, out);
}

// round 2
// speedup vs baseline: 1.0082x; 1.0082x over previous
#include <cuda_runtime.h>

// SphKernel: out[b,v,p,n,c] = g_n(r) * Y_c(rotate(frame, normalize(patch)))
// B=4, V=4096, P=64, NR=3, C=16. 1,048,576 points; 48 f32 out/point (201 MB).
//
// R2: stage only Y[16]+g[3] per point (stride-21 padded shared, conflict-free),
// multiply g*Y during the coalesced float4 write-out. Smem 25KB->10.5KB/block,
// regs capped via __launch_bounds__ -> ~1536 threads/SM for DRAM-feeding MLP.

#define TPB 128
#define PT_STRIDE 21                   // 16 Y + 3 g + 2 pad; odd -> conflict-free
#define VEC4_PER_BLOCK (TPB * 12)      // 48 floats/pt * 128 pts / 4

__global__ __launch_bounds__(TPB, 12)
void sph_kernel(const float* __restrict__ patches,
                const float* __restrict__ frames,
                const float* __restrict__ r,
                float* __restrict__ out)
{
    __shared__ float sh[TPB * PT_STRIDE];   // 10752 B

    const int tid = threadIdx.x;
    const int pt  = blockIdx.x * TPB + tid;   // global point index
    const int fi  = pt >> 6;                  // frame index (P = 64)

    // ---- load & normalize direction ----
    const float px = __ldg(patches + 3 * pt + 0);
    const float py = __ldg(patches + 3 * pt + 1);
    const float pz = __ldg(patches + 3 * pt + 2);
    const float sq  = px * px + py * py + pz * pz;
    const float inv = rsqrtf(fmaxf(sq, 1e-12f));
    const float dx = px * inv, dy = py * inv, dz = pz * inv;

    // ---- rotate into local frame: proj_j = sum_i F[i][j] * d_i ----
    const float* F = frames + 9 * fi;         // warp-uniform -> broadcast LDG
    const float x = __ldg(F + 0) * dx + __ldg(F + 3) * dy + __ldg(F + 6) * dz;
    const float y = __ldg(F + 1) * dx + __ldg(F + 4) * dy + __ldg(F + 7) * dz;
    const float z = __ldg(F + 2) * dx + __ldg(F + 5) * dy + __ldg(F + 8) * dz;

    // ---- spherical harmonics, STS as computed (keeps regs low) ----
    const float x2 = x * x, y2 = y * y, z2 = z * z;
    const float xy = x * y, yz = y * z, zx = z * x;

    float* row = sh + tid * PT_STRIDE;
    row[0]  = 0.28209479177387814f;                          // Y00
    row[1]  = 0.4886025119029199f * z;                       // Y10
    row[2]  = 0.31539156525252005f * (2.f * z2 - x2 - y2);   // Y20
    row[3]  = 0.3731763325901154f * z * (2.f * z2 - 3.f * x2 - 3.f * y2); // Y30
    row[4]  = 0.4886025119029199f * x;                       // Y1_10
    row[5]  = 0.4886025119029199f * y;                       // Y1_11
    row[6]  = 1.0925484305920792f * zx;                      // Y2_10
    row[7]  = 1.0925484305920792f * yz;                      // Y2_11
    row[8]  = 0.4570457994644658f * x * (4.f * z2 - x2 - y2); // Y3_10
    row[9]  = 0.4570457994644658f * y * (4.f * z2 - x2 - y2); // Y3_11
    row[10] = 0.5462742152960396f * (x2 - y2);               // Y2_20
    row[11] = 1.0925484305920792f * xy;                      // Y2_21
    row[12] = 1.4453057213202771f * z * (x2 - y2);           // Y3_20
    row[13] = 2.8906114426405543f * xy * z;                  // Y3_21
    row[14] = 0.5900435899266435f * x * (x2 - 3.f * y2);     // Y3_30
    row[15] = 0.5900435899266435f * y * (3.f * x2 - y2);     // Y3_31

    // ---- gaussian shells: centers {0, 0.5, 1}, exp(4*ln(0.5)*d^2), normalized ----
    const float rv = __ldg(r + pt);
    const float K = -2.772588722239781f;   // 4 * ln(0.5)
    const float d1 = rv - 0.5f, d2 = rv - 1.0f;
    const float g0 = __expf(K * rv * rv);
    const float g1 = __expf(K * d1 * d1);
    const float g2 = __expf(K * d2 * d2);
    const float ginv = 1.0f / (g0 + g1 + g2);
    row[16] = g0 * ginv;
    row[17] = g1 * ginv;
    row[18] = g2 * ginv;

    __syncthreads();

    // ---- coalesced float4 write-out: idx f4 covers [block * 1536, +1536) ----
    float4* out4 = reinterpret_cast<float4*>(out);
    const size_t base = (size_t)blockIdx.x * VEC4_PER_BLOCK;
#pragma unroll
    for (int k = 0; k < 12; k++) {
        const int f4 = k * TPB + tid;      // float4 index within block tile
        const int p  = f4 / 12;            // point within block (12 float4 per point)
        const int r4 = f4 - p * 12;
        const int shell = r4 >> 2;         // 0..2
        const int c  = (r4 & 3) << 2;      // 0,4,8,12
        const float* s = sh + p * PT_STRIDE + c;
        const float g  = sh[p * PT_STRIDE + 16 + shell];
        float4 v = make_float4(g * s[0], g * s[1], g * s[2], g * s[3]);
        out4[base + f4] = v;
    }
}

extern "C" void kernel_launch(void* const* d_in, const int* in_sizes, int n_in,
                              void* d_out, int out_size)
{
    const float* patches = (const float*)d_in[0];  // [4,4096,64,3]
    const float* frames  = (const float*)d_in[1];  // [4,4096,3,3]
    const float* r       = (const float*)d_in[2];  // [4,4096,64]
    float* out = (float*)d_out;                    // [4,4096,64,3,16]

    const int total_points = in_sizes[2];          // 1,048,576
    const int blocks = total_points / TPB;         // 8192

    sph_kernel<<<blocks, TPB>>>(patches, frames, r, out);
}

// round 3
// speedup vs baseline: 1.0107x; 1.0025x over previous
#include <cuda_runtime.h>

// SphKernel: out[b,v,p,n,c] = g_n(r) * Y_c(rotate(frame, normalize(patch)))
// B=4, V=4096, P=64, NR=3, C=16. 1,048,576 points; 48 f32 out/point (201 MB).
//
// R3: fully vectorized shared staging. Row = 5 float4 per point
// (4x Y-quad + 1x g-vec), stride 20 floats -> 16B-aligned, conflict-free
// STS.128/LDS.128. Write-out: LDS.128 + LDS.32(g) + 4 FMUL + STG.128.

#define TPB 128
#define PT_F4 5                      // float4 chunks per point
#define PT_STRIDE 20                 // floats per point row
#define VEC4_PER_BLOCK (TPB * 12)    // 1536 float4 per block

__global__ __launch_bounds__(TPB, 12)
void sph_kernel(const float* __restrict__ patches,
                const float* __restrict__ frames,
                const float* __restrict__ r,
                float* __restrict__ out)
{
    __shared__ float4 sh4[TPB * PT_F4];           // 10240 B
    float* sh = reinterpret_cast<float*>(sh4);

    const int tid = threadIdx.x;
    const int pt  = blockIdx.x * TPB + tid;       // global point index
    const int fi  = pt >> 6;                      // frame index (P = 64)

    // ---- load & normalize direction ----
    const float px = __ldg(patches + 3 * pt + 0);
    const float py = __ldg(patches + 3 * pt + 1);
    const float pz = __ldg(patches + 3 * pt + 2);
    const float sq  = px * px + py * py + pz * pz;
    const float inv = rsqrtf(fmaxf(sq, 1e-12f));
    const float dx = px * inv, dy = py * inv, dz = pz * inv;

    // ---- rotate into local frame: proj_j = sum_i F[i][j] * d_i ----
    const float* F = frames + 9 * fi;             // warp-uniform -> broadcast
    const float x = __ldg(F + 0) * dx + __ldg(F + 3) * dy + __ldg(F + 6) * dz;
    const float y = __ldg(F + 1) * dx + __ldg(F + 4) * dy + __ldg(F + 7) * dz;
    const float z = __ldg(F + 2) * dx + __ldg(F + 5) * dy + __ldg(F + 8) * dz;

    // ---- spherical harmonics (reference channel order) ----
    const float x2 = x * x, y2 = y * y, z2 = z * z;
    const float xy = x * y, yz = y * z, zx = z * x;

    float4* row4 = sh4 + tid * PT_F4;
    row4[0] = make_float4(
        0.28209479177387814f,                                   // Y00
        0.4886025119029199f * z,                                // Y10
        0.31539156525252005f * (2.f * z2 - x2 - y2),            // Y20
        0.3731763325901154f * z * (2.f * z2 - 3.f * x2 - 3.f * y2)); // Y30
    row4[1] = make_float4(
        0.4886025119029199f * x,                                // Y1_10
        0.4886025119029199f * y,                                // Y1_11
        1.0925484305920792f * zx,                               // Y2_10
        1.0925484305920792f * yz);                              // Y2_11
    row4[2] = make_float4(
        0.4570457994644658f * x * (4.f * z2 - x2 - y2),         // Y3_10
        0.4570457994644658f * y * (4.f * z2 - x2 - y2),         // Y3_11
        0.5462742152960396f * (x2 - y2),                        // Y2_20
        1.0925484305920792f * xy);                              // Y2_21
    row4[3] = make_float4(
        1.4453057213202771f * z * (x2 - y2),                    // Y3_20
        2.8906114426405543f * xy * z,                           // Y3_21
        0.5900435899266435f * x * (x2 - 3.f * y2),              // Y3_30
        0.5900435899266435f * y * (3.f * x2 - y2));             // Y3_31

    // ---- gaussian shells: centers {0, 0.5, 1}, normalized ----
    const float rv = __ldg(r + pt);
    const float K = -2.772588722239781f;          // 4 * ln(0.5)
    const float d1 = rv - 0.5f, d2 = rv - 1.0f;
    const float g0 = __expf(K * rv * rv);
    const float g1 = __expf(K * d1 * d1);
    const float g2 = __expf(K * d2 * d2);
    const float ginv = __fdividef(1.0f, g0 + g1 + g2);
    row4[4] = make_float4(g0 * ginv, g1 * ginv, g2 * ginv, 0.0f);

    __syncthreads();

    // ---- coalesced float4 write-out ----
    float4* out4 = reinterpret_cast<float4*>(out);
    const size_t base = (size_t)blockIdx.x * VEC4_PER_BLOCK;
#pragma unroll
    for (int k = 0; k < 12; k++) {
        const int f4 = k * TPB + tid;       // float4 index within block tile
        const int p  = f4 / 12;             // point within block
        const int r4 = f4 - p * 12;
        const int shell = r4 >> 2;          // 0..2
        const int cg    = r4 & 3;           // Y quad 0..3
        const float4 Yv = sh4[p * PT_F4 + cg];            // LDS.128
        const float g   = sh[p * PT_STRIDE + 16 + shell]; // LDS.32 (broadcasty)
        out4[base + f4] = make_float4(g * Yv.x, g * Yv.y, g * Yv.z, g * Yv.w);
    }
}

extern "C" void kernel_launch(void* const* d_in, const int* in_sizes, int n_in,
                              void* d_out, int out_size)
{
    const float* patches = (const float*)d_in[0];  // [4,4096,64,3]
    const float* frames  = (const float*)d_in[1];  // [4,4096,3,3]
    const float* r       = (const float*)d_in[2];  // [4,4096,64]
    float* out = (float*)d_out;                    // [4,4096,64,3,16]

    const int total_points = in_sizes[2];          // 1,048,576
    const int blocks = total_points / TPB;         // 8192

    sph_kernel<<<blocks, TPB>>>(patches, frames, r, out);
}

// round 4
// speedup vs baseline: 1.1827x; 1.1702x over previous
#include <cuda_runtime.h>

// SphKernel: out[b,v,p,n,c] = g_n(r) * Y_c(rotate(frame, normalize(patch)))
// B=4, V=4096, P=64, NR=3, C=16. 1,048,576 points; 48 f32 out/point (201 MB).
//
// R4: same vectorized-staging structure as R3, but force 16 blocks/SM
// (__launch_bounds__(128,16) -> 32 regs, 2048 threads/SM) for more
// store-level parallelism, and use streaming (__stcs) output stores since
// the output is write-once.

#define TPB 128
#define PT_F4 5                      // float4 chunks per point
#define PT_STRIDE 20                 // floats per point row
#define VEC4_PER_BLOCK (TPB * 12)    // 1536 float4 per block

__global__ __launch_bounds__(TPB, 16)
void sph_kernel(const float* __restrict__ patches,
                const float* __restrict__ frames,
                const float* __restrict__ r,
                float* __restrict__ out)
{
    __shared__ float4 sh4[TPB * PT_F4];           // 10240 B
    float* sh = reinterpret_cast<float*>(sh4);

    const int tid = threadIdx.x;
    const int pt  = blockIdx.x * TPB + tid;       // global point index
    const int fi  = pt >> 6;                      // frame index (P = 64)

    // ---- load & normalize direction ----
    const float px = __ldg(patches + 3 * pt + 0);
    const float py = __ldg(patches + 3 * pt + 1);
    const float pz = __ldg(patches + 3 * pt + 2);
    const float sq  = px * px + py * py + pz * pz;
    const float inv = rsqrtf(fmaxf(sq, 1e-12f));
    const float dx = px * inv, dy = py * inv, dz = pz * inv;

    // ---- rotate into local frame: proj_j = sum_i F[i][j] * d_i ----
    const float* F = frames + 9 * fi;             // warp-uniform -> broadcast
    const float x = __ldg(F + 0) * dx + __ldg(F + 3) * dy + __ldg(F + 6) * dz;
    const float y = __ldg(F + 1) * dx + __ldg(F + 4) * dy + __ldg(F + 7) * dz;
    const float z = __ldg(F + 2) * dx + __ldg(F + 5) * dy + __ldg(F + 8) * dz;

    // ---- spherical harmonics (reference channel order), STS as computed ----
    const float x2 = x * x, y2 = y * y, z2 = z * z;
    const float xy = x * y, yz = y * z, zx = z * x;

    float4* row4 = sh4 + tid * PT_F4;
    row4[0] = make_float4(
        0.28209479177387814f,                                   // Y00
        0.4886025119029199f * z,                                // Y10
        0.31539156525252005f * (2.f * z2 - x2 - y2),            // Y20
        0.3731763325901154f * z * (2.f * z2 - 3.f * x2 - 3.f * y2)); // Y30
    row4[1] = make_float4(
        0.4886025119029199f * x,                                // Y1_10
        0.4886025119029199f * y,                                // Y1_11
        1.0925484305920792f * zx,                               // Y2_10
        1.0925484305920792f * yz);                              // Y2_11
    row4[2] = make_float4(
        0.4570457994644658f * x * (4.f * z2 - x2 - y2),         // Y3_10
        0.4570457994644658f * y * (4.f * z2 - x2 - y2),         // Y3_11
        0.5462742152960396f * (x2 - y2),                        // Y2_20
        1.0925484305920792f * xy);                              // Y2_21
    row4[3] = make_float4(
        1.4453057213202771f * z * (x2 - y2),                    // Y3_20
        2.8906114426405543f * xy * z,                           // Y3_21
        0.5900435899266435f * x * (x2 - 3.f * y2),              // Y3_30
        0.5900435899266435f * y * (3.f * x2 - y2));             // Y3_31

    // ---- gaussian shells: centers {0, 0.5, 1}, normalized ----
    const float rv = __ldg(r + pt);
    const float K = -2.772588722239781f;          // 4 * ln(0.5)
    const float d1 = rv - 0.5f, d2 = rv - 1.0f;
    const float g0 = __expf(K * rv * rv);
    const float g1 = __expf(K * d1 * d1);
    const float g2 = __expf(K * d2 * d2);
    const float ginv = __fdividef(1.0f, g0 + g1 + g2);
    row4[4] = make_float4(g0 * ginv, g1 * ginv, g2 * ginv, 0.0f);

    __syncthreads();

    // ---- coalesced float4 streaming write-out ----
    float4* out4 = reinterpret_cast<float4*>(out);
    const size_t base = (size_t)blockIdx.x * VEC4_PER_BLOCK;
#pragma unroll
    for (int k = 0; k < 12; k++) {
        const int f4 = k * TPB + tid;       // float4 index within block tile
        const int p  = f4 / 12;             // point within block
        const int r4 = f4 - p * 12;
        const int shell = r4 >> 2;          // 0..2
        const int cg    = r4 & 3;           // Y quad 0..3
        const float4 Yv = sh4[p * PT_F4 + cg];            // LDS.128
        const float g   = sh[p * PT_STRIDE + 16 + shell]; // LDS.32 (broadcasty)
        __stcs(out4 + base + f4,
               make_float4(g * Yv.x, g * Yv.y, g * Yv.z, g * Yv.w));
    }
}

extern "C" void kernel_launch(void* const* d_in, const int* in_sizes, int n_in,
                              void* d_out, int out_size)
{
    const float* patches = (const float*)d_in[0];  // [4,4096,64,3]
    const float* frames  = (const float*)d_in[1];  // [4,4096,3,3]
    const float* r       = (const float*)d_in[2];  // [4,4096,64]
    float* out = (float*)d_out;                    // [4,4096,64,3,16]

    const int total_points = in_sizes[2];          // 1,048,576
    const int blocks = total_points / TPB;         // 8192

    sph_kernel<<<blocks, TPB>>>(patches, frames, r, out);
}